// round 13
// baseline (speedup 1.0000x reference)
#include <cuda_runtime.h>
#include <math.h>

#define T_STEPS 2048
#define BATCH   64
#define IN_DIM  27
#define H1      400
#define H2      200
#define GRID_R  148          // 104 x 3 units + 44 x 2 units = 400
#define K4      (H1 / 4)

// ---------------- device scratch (static; zero-init) ----------------
static __device__ float g_xw[(size_t)T_STEPS * 4 * H1 * BATCH];   // [t][row1600][b]
static __device__ float g_hr[(size_t)(T_STEPS + 1) * H1 * BATCH]; // [t][k>>2][b][k&3]
static __device__ unsigned int g_prog[GRID_R];                     // per-CTA progress

__device__ __forceinline__ void ffma2(unsigned long long &acc,
                                      unsigned long long a, unsigned long long b) {
    asm("fma.rn.f32x2 %0, %1, %2, %0;" : "+l"(acc) : "l"(a), "l"(b));
}
__device__ __forceinline__ float lo32(unsigned long long v) { return __uint_as_float((unsigned)v); }
__device__ __forceinline__ float hi32(unsigned long long v) { return __uint_as_float((unsigned)(v >> 32)); }

__device__ __forceinline__ unsigned ld_acq(const unsigned* p) {
    unsigned v;
    asm volatile("ld.acquire.gpu.u32 %0, [%1];" : "=r"(v) : "l"(p));
    return v;
}
__device__ __forceinline__ int prod_of_unit(int u) {
    return (u < 312) ? (u / 3) : (104 + (u - 312) / 2);
}

// profiling spacers so ncu -s 5 lands on k_rec
__global__ void k_noop() {}

// =====================================================================
// Kernel 1: xw[t][r][b] = word[t,b,:] . W_ih[r,:] + b_ih[r] + b_hh[r]
// grid (25, 2048), block 256. Resets per-CTA progress counters.
// =====================================================================
__global__ void __launch_bounds__(256) k_xw(const float* __restrict__ word,
                                            const float* __restrict__ Wih,
                                            const float* __restrict__ bih,
                                            const float* __restrict__ bhh) {
    __shared__ float xs[IN_DIM * 68];
    __shared__ float ws[64 * 28];
    __shared__ float bs[64];
    const int t = blockIdx.y;
    const int rbase = blockIdx.x * 64;
    const int tid = threadIdx.x;

    if (blockIdx.x == 0 && blockIdx.y == 0 && tid < GRID_R) g_prog[tid] = 0u;

    for (int j = tid; j < BATCH * IN_DIM; j += 256) {
        int b = j / IN_DIM, i = j - b * IN_DIM;
        xs[i * 68 + b] = word[(size_t)t * (BATCH * IN_DIM) + j];
    }
    for (int j = tid; j < 64 * IN_DIM; j += 256) {
        int r = j / IN_DIM, i = j - r * IN_DIM;
        ws[r * 28 + i] = Wih[(size_t)(rbase + r) * IN_DIM + i];
    }
    if (tid < 64) bs[tid] = bih[rbase + tid] + bhh[rbase + tid];
    __syncthreads();

    const int rq = tid >> 4;
    const int bq = (tid & 15) * 4;
    float acc[4][4];
    #pragma unroll
    for (int r = 0; r < 4; r++) {
        float bv = bs[rq * 4 + r];
        #pragma unroll
        for (int b = 0; b < 4; b++) acc[r][b] = bv;
    }
    #pragma unroll 3
    for (int i = 0; i < IN_DIM; i++) {
        float4 xv = *(const float4*)&xs[i * 68 + bq];
        #pragma unroll
        for (int r = 0; r < 4; r++) {
            float w = ws[(rq * 4 + r) * 28 + i];
            acc[r][0] += w * xv.x; acc[r][1] += w * xv.y;
            acc[r][2] += w * xv.z; acc[r][3] += w * xv.w;
        }
    }
    size_t base = ((size_t)t * (4 * H1) + rbase) * BATCH;
    #pragma unroll
    for (int r = 0; r < 4; r++) {
        float4 v = make_float4(acc[r][0], acc[r][1], acc[r][2], acc[r][3]);
        *(float4*)&g_xw[base + (size_t)(rq * 4 + r) * BATCH + bq] = v;
    }
}

// =====================================================================
// Kernel 2: persistent recurrence. grid 148, block 256, 1 CTA/SM.
// R4 structure; central barrier replaced by producer-consumer dataflow:
// each CTA publishes g_prog[bid]=t+1 (plain release store, NO atomic RMW)
// after its h(t+1) slice is visible; each warp acquires only the
// progress of the producers of its k-chunk, in 2 chunks to overlap.
// =====================================================================
template<int NU>
__device__ __forceinline__ void rec_body(const float* __restrict__ Whh,
                                         int u0, int bid, float* ws, float* pr) {
    constexpr int R = 4 * NU;
    const int tid  = threadIdx.x;
    const int lane = tid & 31;
    const int wid  = tid >> 5;
    const int ks   = wid & 3;                // k-split 0..3 (25 k4 each)
    const int bg   = wid >> 2;               // batch group 0..1
    const int b    = bg * 32 + lane;

    for (int idx = tid; idx < R * H1; idx += 256) {
        int lr = idx / H1, k = idx - lr * H1;
        int g = lr / NU, q = lr - g * NU;
        ws[lr * H1 + k] = Whh[(size_t)(g * H1 + u0 + q) * H1 + k];
    }

    const int cb = tid & 63;
    const int q  = tid >> 6;
    const int uu = u0 + (q < NU ? q : NU - 1);
    const size_t hr_off = (size_t)(uu >> 2) * 256 + cb * 4 + (uu & 3);
    float c_val = 0.0f;

    // per-warp producer poll targets for the 2 k-chunks
    const int k4lo = ks * 25;
    const int cu0  = 4 * k4lo;
    const int pp0  = min(prod_of_unit(cu0)      + lane, prod_of_unit(cu0 + 51));
    const int pp1  = min(prod_of_unit(cu0 + 52) + lane, prod_of_unit(cu0 + 99));

    __syncthreads();

    // prefetch xw for step 0
    float xw0 = 0.f, xw1 = 0.f, xw2 = 0.f, xw3 = 0.f;
    if (q < NU) {
        const float* xp = g_xw;
        xw0 = __ldcg(&xp[(size_t)(0 * H1 + uu) * BATCH + cb]);
        xw1 = __ldcg(&xp[(size_t)(1 * H1 + uu) * BATCH + cb]);
        xw2 = __ldcg(&xp[(size_t)(2 * H1 + uu) * BATCH + cb]);
        xw3 = __ldcg(&xp[(size_t)(3 * H1 + uu) * BATCH + cb]);
    }

    for (int t = 0; t < T_STEPS; t++) {
        const unsigned need = (unsigned)t;
        unsigned long long acc[R];
        #pragma unroll
        for (int lr = 0; lr < R; lr++) acc[lr] = 0ull;
        const float* hbase = g_hr + (size_t)t * (H1 * BATCH);

        // ---- wait chunk0 producers (backoff off fast path), dots [0,13) ----
        if (__any_sync(0xffffffffu, ld_acq(&g_prog[pp0]) < need)) {
            while (__any_sync(0xffffffffu, ld_acq(&g_prog[pp0]) < need)) __nanosleep(20);
        }
        {
            ulonglong2 h_cur = __ldcg((const ulonglong2*)(hbase + k4lo * 256 + b * 4));
            #pragma unroll 4
            for (int i = 0; i < 13; i++) {
                ulonglong2 h4 = h_cur;
                if (i < 12)
                    h_cur = __ldcg((const ulonglong2*)(hbase + (k4lo + i + 1) * 256 + b * 4));
                const int k4 = k4lo + i;
                #pragma unroll
                for (int lr = 0; lr < R; lr++) {
                    ulonglong2 w2 = *(const ulonglong2*)&ws[lr * H1 + k4 * 4];
                    ffma2(acc[lr], h4.x, w2.x);
                    ffma2(acc[lr], h4.y, w2.y);
                }
            }
        }
        // ---- wait chunk1 producers, dots [13,25) ----
        if (__any_sync(0xffffffffu, ld_acq(&g_prog[pp1]) < need)) {
            while (__any_sync(0xffffffffu, ld_acq(&g_prog[pp1]) < need)) __nanosleep(20);
        }
        {
            ulonglong2 h_cur = __ldcg((const ulonglong2*)(hbase + (k4lo + 13) * 256 + b * 4));
            #pragma unroll 4
            for (int i = 13; i < 25; i++) {
                ulonglong2 h4 = h_cur;
                if (i < 24)
                    h_cur = __ldcg((const ulonglong2*)(hbase + (k4lo + i + 1) * 256 + b * 4));
                const int k4 = k4lo + i;
                #pragma unroll
                for (int lr = 0; lr < R; lr++) {
                    ulonglong2 w2 = *(const ulonglong2*)&ws[lr * H1 + k4 * 4];
                    ffma2(acc[lr], h4.x, w2.x);
                    ffma2(acc[lr], h4.y, w2.y);
                }
            }
        }
        #pragma unroll
        for (int lr = 0; lr < R; lr++)
            pr[(ks * R + lr) * 64 + b] = lo32(acc[lr]) + hi32(acc[lr]);
        __syncthreads();

        // ---- combine: LSTM cell for (unit uu, batch cb) ----
        if (q < NU) {
            float g0 = xw0, g1 = xw1, g2 = xw2, g3 = xw3;
            #pragma unroll
            for (int s = 0; s < 4; s++) {
                g0 += pr[(s * R + 0 * NU + q) * 64 + cb];
                g1 += pr[(s * R + 1 * NU + q) * 64 + cb];
                g2 += pr[(s * R + 2 * NU + q) * 64 + cb];
                g3 += pr[(s * R + 3 * NU + q) * 64 + cb];
            }
            float iv = 1.0f / (1.0f + expf(-g0));
            float fv = 1.0f / (1.0f + expf(-g1));
            float gv = tanhf(g2);
            float ov = 1.0f / (1.0f + expf(-g3));
            float cn = fv * c_val + iv * gv;
            float hn = ov * tanhf(cn);
            c_val = fmaxf(cn, 0.0f);
            g_hr[(size_t)(t + 1) * (H1 * BATCH) + hr_off] = fmaxf(hn, 0.0f);
        }
        __syncthreads();          // all combine stores issued before publish

        // ---- publish progress: plain release store, no RMW ----
        if (tid == 0) {
            __threadfence();
            asm volatile("st.release.gpu.u32 [%0], %1;"
                         :: "l"(&g_prog[bid]), "r"((unsigned)(t + 1)) : "memory");
        }

        // ---- prefetch xw for step t+1 ----
        if (q < NU && t + 1 < T_STEPS) {
            const float* xp = g_xw + (size_t)(t + 1) * (4 * H1) * BATCH;
            xw0 = __ldcg(&xp[(size_t)(0 * H1 + uu) * BATCH + cb]);
            xw1 = __ldcg(&xp[(size_t)(1 * H1 + uu) * BATCH + cb]);
            xw2 = __ldcg(&xp[(size_t)(2 * H1 + uu) * BATCH + cb]);
            xw3 = __ldcg(&xp[(size_t)(3 * H1 + uu) * BATCH + cb]);
        }
    }
}

__global__ void __launch_bounds__(256, 1) k_rec(const float* __restrict__ Whh) {
    __shared__ float ws[12 * H1];
    __shared__ float pr[4 * 12 * 64];
    const int bid = blockIdx.x;
    if (bid < 104) rec_body<3>(Whh, bid * 3, bid, ws, pr);
    else           rec_body<2>(Whh, 312 + (bid - 104) * 2, bid, ws, pr);
}

// =====================================================================
// Kernel 3: MLP head per timestep. grid 2048, block 256.
// =====================================================================
#define HS_F 25600
#define HEAD_SMEM_B ((HS_F + H2 * BATCH) * 4)

__global__ void __launch_bounds__(256) k_head(const float* __restrict__ Wfc,
                                              const float* __restrict__ bfc,
                                              const float* __restrict__ Wout,
                                              const float* __restrict__ bout,
                                              float* __restrict__ out) {
    extern __shared__ float sm[];
    float* hs  = sm;
    float* hid = sm + HS_F;
    const int t = blockIdx.x;
    const int tid = threadIdx.x;

    const float4* hsrc = (const float4*)(g_hr + (size_t)(t + 1) * (H1 * BATCH));
    for (int i = tid; i < (H1 * BATCH) / 4; i += 256)
        ((float4*)hs)[i] = hsrc[i];
    __syncthreads();

    const int jrow = tid >> 4;
    const int bq   = (tid & 15) * 4;
    for (int j = jrow; j < H2; j += 16) {
        float bv = bfc[j];
        float4 acc = make_float4(bv, bv, bv, bv);
        const float4* wr = (const float4*)(Wfc + (size_t)j * H1);
        #pragma unroll 4
        for (int k4 = 0; k4 < K4; k4++) {
            float4 w4 = wr[k4];
            float4 h0 = *(const float4*)&hs[k4 * 256 + (bq + 0) * 4];
            float4 h1 = *(const float4*)&hs[k4 * 256 + (bq + 1) * 4];
            float4 h2 = *(const float4*)&hs[k4 * 256 + (bq + 2) * 4];
            float4 h3 = *(const float4*)&hs[k4 * 256 + (bq + 3) * 4];
            acc.x += w4.x * h0.x + w4.y * h0.y + w4.z * h0.z + w4.w * h0.w;
            acc.y += w4.x * h1.x + w4.y * h1.y + w4.z * h1.z + w4.w * h1.w;
            acc.z += w4.x * h2.x + w4.y * h2.y + w4.z * h2.z + w4.w * h2.w;
            acc.w += w4.x * h3.x + w4.y * h3.y + w4.z * h3.z + w4.w * h3.w;
        }
        acc.x = fmaxf(acc.x, 0.f); acc.y = fmaxf(acc.y, 0.f);
        acc.z = fmaxf(acc.z, 0.f); acc.w = fmaxf(acc.w, 0.f);
        *(float4*)&hid[j * BATCH + bq] = acc;
    }
    __syncthreads();

    if (tid < BATCH) {
        float s = bout[0];
        #pragma unroll 8
        for (int j = 0; j < H2; j++)
            s += hid[j * BATCH + tid] * Wout[j];
        out[(size_t)t * BATCH + tid] = 1.0f / (1.0f + expf(-s));
    }
}

// =====================================================================
extern "C" void kernel_launch(void* const* d_in, const int* in_sizes, int n_in,
                              void* d_out, int out_size) {
    const float* word = (const float*)d_in[0];
    const float* Wih  = (const float*)d_in[1];
    const float* Whh  = (const float*)d_in[2];
    const float* bih  = (const float*)d_in[3];
    const float* bhh  = (const float*)d_in[4];
    const float* Wfc  = (const float*)d_in[5];
    const float* bfc  = (const float*)d_in[6];
    const float* Wout = (const float*)d_in[7];
    const float* bout = (const float*)d_in[8];
    float* out = (float*)d_out;

    cudaFuncSetAttribute(k_head, cudaFuncAttributeMaxDynamicSharedMemorySize, HEAD_SMEM_B);

    // spacers so ncu -s 5 captures k_rec instead of k_xw/k_head
    k_noop<<<1, 32>>>();
    k_noop<<<1, 32>>>();
    k_noop<<<1, 32>>>();
    k_xw<<<dim3(25, T_STEPS), 256>>>(word, Wih, bih, bhh);
    k_rec<<<GRID_R, 256>>>(Whh);
    k_head<<<T_STEPS, 256, HEAD_SMEM_B>>>(Wfc, bfc, Wout, bout, out);
}

// round 14
// speedup vs baseline: 1.5469x; 1.5469x over previous
#include <cuda_runtime.h>
#include <math.h>

#define T_STEPS 2048
#define BATCH   64
#define IN_DIM  27
#define H1      400
#define H2      200
#define GRID_R  148          // 104 x 3 units + 44 x 2 units = 400
#define K4      (H1 / 4)

// ---------------- device scratch (static; zero-init) ----------------
static __device__ float g_xw[(size_t)T_STEPS * 4 * H1 * BATCH];   // [t][row1600][b]
static __device__ float g_hr[(size_t)(T_STEPS + 1) * H1 * BATCH]; // [t][k>>2][b][k&3]
static __device__ unsigned int g_bar;

__device__ __forceinline__ void ffma2(unsigned long long &acc,
                                      unsigned long long a, unsigned long long b) {
    asm("fma.rn.f32x2 %0, %1, %2, %0;" : "+l"(acc) : "l"(a), "l"(b));
}
__device__ __forceinline__ float lo32(unsigned long long v) { return __uint_as_float((unsigned)v); }
__device__ __forceinline__ float hi32(unsigned long long v) { return __uint_as_float((unsigned)(v >> 32)); }

// profiling spacer (harness has 2 pre-launches; k_xw,noop,noop puts k_rec at #6 for -s 5)
__global__ void k_noop() {}

// =====================================================================
// Kernel 1: xw[t][r][b] = word[t,b,:] . W_ih[r,:] + b_ih[r] + b_hh[r]
// grid (25, 2048), block 256. Also resets the barrier counter.
// =====================================================================
__global__ void __launch_bounds__(256) k_xw(const float* __restrict__ word,
                                            const float* __restrict__ Wih,
                                            const float* __restrict__ bih,
                                            const float* __restrict__ bhh) {
    __shared__ float xs[IN_DIM * 68];
    __shared__ float ws[64 * 28];
    __shared__ float bs[64];
    const int t = blockIdx.y;
    const int rbase = blockIdx.x * 64;
    const int tid = threadIdx.x;

    if (blockIdx.x == 0 && blockIdx.y == 0 && tid == 0) g_bar = 0u;

    for (int j = tid; j < BATCH * IN_DIM; j += 256) {
        int b = j / IN_DIM, i = j - b * IN_DIM;
        xs[i * 68 + b] = word[(size_t)t * (BATCH * IN_DIM) + j];
    }
    for (int j = tid; j < 64 * IN_DIM; j += 256) {
        int r = j / IN_DIM, i = j - r * IN_DIM;
        ws[r * 28 + i] = Wih[(size_t)(rbase + r) * IN_DIM + i];
    }
    if (tid < 64) bs[tid] = bih[rbase + tid] + bhh[rbase + tid];
    __syncthreads();

    const int rq = tid >> 4;
    const int bq = (tid & 15) * 4;
    float acc[4][4];
    #pragma unroll
    for (int r = 0; r < 4; r++) {
        float bv = bs[rq * 4 + r];
        #pragma unroll
        for (int b = 0; b < 4; b++) acc[r][b] = bv;
    }
    #pragma unroll 3
    for (int i = 0; i < IN_DIM; i++) {
        float4 xv = *(const float4*)&xs[i * 68 + bq];
        #pragma unroll
        for (int r = 0; r < 4; r++) {
            float w = ws[(rq * 4 + r) * 28 + i];
            acc[r][0] += w * xv.x; acc[r][1] += w * xv.y;
            acc[r][2] += w * xv.z; acc[r][3] += w * xv.w;
        }
    }
    size_t base = ((size_t)t * (4 * H1) + rbase) * BATCH;
    #pragma unroll
    for (int r = 0; r < 4; r++) {
        float4 v = make_float4(acc[r][0], acc[r][1], acc[r][2], acc[r][3]);
        *(float4*)&g_xw[base + (size_t)(rq * 4 + r) * BATCH + bq] = v;
    }
}

// =====================================================================
// Kernel 2: persistent recurrence. grid 148, block 256, 1 CTA/SM.
// CHAMPION (R4) structure exactly; only change: h prefetch 1-deep -> 4-deep
// register ring (full unroll), to cover loaded-L2 latency.
// =====================================================================
template<int NU>
__device__ __forceinline__ void rec_body(const float* __restrict__ Whh,
                                         int u0, float* ws, float* pr) {
    constexpr int R = 4 * NU;
    const int tid  = threadIdx.x;
    const int lane = tid & 31;
    const int wid  = tid >> 5;
    const int ks   = wid & 3;                // k-split 0..3 (25 k4 each)
    const int bg   = wid >> 2;               // batch group 0..1
    const int b    = bg * 32 + lane;

    for (int idx = tid; idx < R * H1; idx += 256) {
        int lr = idx / H1, k = idx - lr * H1;
        int g = lr / NU, q = lr - g * NU;
        ws[lr * H1 + k] = Whh[(size_t)(g * H1 + u0 + q) * H1 + k];
    }

    const int cb = tid & 63;
    const int q  = tid >> 6;
    const int uu = u0 + (q < NU ? q : NU - 1);
    const size_t hr_off = (size_t)(uu >> 2) * 256 + cb * 4 + (uu & 3);
    float c_val = 0.0f;

    __syncthreads();

    const int k4lo = ks * 25;

    for (int t = 0; t < T_STEPS; t++) {
        // ---- prefetch xw for combine (latency hidden under dots) ----
        float xw0 = 0.f, xw1 = 0.f, xw2 = 0.f, xw3 = 0.f;
        if (q < NU) {
            const float* xp = g_xw + (size_t)t * (4 * H1) * BATCH;
            xw0 = __ldcg(&xp[(size_t)(0 * H1 + uu) * BATCH + cb]);
            xw1 = __ldcg(&xp[(size_t)(1 * H1 + uu) * BATCH + cb]);
            xw2 = __ldcg(&xp[(size_t)(2 * H1 + uu) * BATCH + cb]);
            xw3 = __ldcg(&xp[(size_t)(3 * H1 + uu) * BATCH + cb]);
        }

        // ---- dots: acc[lr] over this warp's k-range; 4-deep h prefetch ring ----
        unsigned long long acc[R];
        #pragma unroll
        for (int lr = 0; lr < R; lr++) acc[lr] = 0ull;

        const float* hbase = g_hr + (size_t)t * (H1 * BATCH);
        ulonglong2 hbuf[4];
        #pragma unroll
        for (int j = 0; j < 4; j++)
            hbuf[j] = __ldcg((const ulonglong2*)(hbase + (k4lo + j) * 256 + b * 4));

        #pragma unroll
        for (int i = 0; i < 25; i++) {
            ulonglong2 h4 = hbuf[i & 3];
            if (i + 4 < 25)
                hbuf[i & 3] = __ldcg((const ulonglong2*)(hbase + (k4lo + i + 4) * 256 + b * 4));
            const int k4 = k4lo + i;
            #pragma unroll
            for (int lr = 0; lr < R; lr++) {
                ulonglong2 w2 = *(const ulonglong2*)&ws[lr * H1 + k4 * 4];
                ffma2(acc[lr], h4.x, w2.x);
                ffma2(acc[lr], h4.y, w2.y);
            }
        }
        #pragma unroll
        for (int lr = 0; lr < R; lr++)
            pr[(ks * R + lr) * 64 + b] = lo32(acc[lr]) + hi32(acc[lr]);
        __syncthreads();

        // ---- combine: LSTM cell for (unit uu, batch cb) ----
        if (q < NU) {
            float g0 = xw0, g1 = xw1, g2 = xw2, g3 = xw3;
            #pragma unroll
            for (int s = 0; s < 4; s++) {
                g0 += pr[(s * R + 0 * NU + q) * 64 + cb];
                g1 += pr[(s * R + 1 * NU + q) * 64 + cb];
                g2 += pr[(s * R + 2 * NU + q) * 64 + cb];
                g3 += pr[(s * R + 3 * NU + q) * 64 + cb];
            }
            float iv = 1.0f / (1.0f + expf(-g0));
            float fv = 1.0f / (1.0f + expf(-g1));
            float gv = tanhf(g2);
            float ov = 1.0f / (1.0f + expf(-g3));
            float cn = fv * c_val + iv * gv;
            float hn = ov * tanhf(cn);
            c_val = fmaxf(cn, 0.0f);
            g_hr[(size_t)(t + 1) * (H1 * BATCH) + hr_off] = fmaxf(hn, 0.0f);
        }

        // ---- grid barrier: R4-proven (fence, sync, tid0 arrive+poll, sync) ----
        __threadfence();
        __syncthreads();
        if (tid == 0) {
            atomicAdd(&g_bar, 1u);
            const unsigned target = (unsigned)(t + 1) * GRID_R;
            unsigned v;
            do {
                asm volatile("ld.acquire.gpu.u32 %0, [%1];" : "=r"(v) : "l"(&g_bar));
            } while (v < target);
        }
        __syncthreads();
    }
}

__global__ void __launch_bounds__(256, 1) k_rec(const float* __restrict__ Whh) {
    __shared__ float ws[12 * H1];
    __shared__ float pr[4 * 12 * 64];
    const int bid = blockIdx.x;
    if (bid < 104) rec_body<3>(Whh, bid * 3, ws, pr);
    else           rec_body<2>(Whh, 312 + (bid - 104) * 2, ws, pr);
}

// =====================================================================
// Kernel 3: MLP head per timestep. grid 2048, block 256.
// =====================================================================
#define HS_F 25600
#define HEAD_SMEM_B ((HS_F + H2 * BATCH) * 4)

__global__ void __launch_bounds__(256) k_head(const float* __restrict__ Wfc,
                                              const float* __restrict__ bfc,
                                              const float* __restrict__ Wout,
                                              const float* __restrict__ bout,
                                              float* __restrict__ out) {
    extern __shared__ float sm[];
    float* hs  = sm;
    float* hid = sm + HS_F;
    const int t = blockIdx.x;
    const int tid = threadIdx.x;

    const float4* hsrc = (const float4*)(g_hr + (size_t)(t + 1) * (H1 * BATCH));
    for (int i = tid; i < (H1 * BATCH) / 4; i += 256)
        ((float4*)hs)[i] = hsrc[i];
    __syncthreads();

    const int jrow = tid >> 4;
    const int bq   = (tid & 15) * 4;
    for (int j = jrow; j < H2; j += 16) {
        float bv = bfc[j];
        float4 acc = make_float4(bv, bv, bv, bv);
        const float4* wr = (const float4*)(Wfc + (size_t)j * H1);
        #pragma unroll 4
        for (int k4 = 0; k4 < K4; k4++) {
            float4 w4 = wr[k4];
            float4 h0 = *(const float4*)&hs[k4 * 256 + (bq + 0) * 4];
            float4 h1 = *(const float4*)&hs[k4 * 256 + (bq + 1) * 4];
            float4 h2 = *(const float4*)&hs[k4 * 256 + (bq + 2) * 4];
            float4 h3 = *(const float4*)&hs[k4 * 256 + (bq + 3) * 4];
            acc.x += w4.x * h0.x + w4.y * h0.y + w4.z * h0.z + w4.w * h0.w;
            acc.y += w4.x * h1.x + w4.y * h1.y + w4.z * h1.z + w4.w * h1.w;
            acc.z += w4.x * h2.x + w4.y * h2.y + w4.z * h2.z + w4.w * h2.w;
            acc.w += w4.x * h3.x + w4.y * h3.y + w4.z * h3.z + w4.w * h3.w;
        }
        acc.x = fmaxf(acc.x, 0.f); acc.y = fmaxf(acc.y, 0.f);
        acc.z = fmaxf(acc.z, 0.f); acc.w = fmaxf(acc.w, 0.f);
        *(float4*)&hid[j * BATCH + bq] = acc;
    }
    __syncthreads();

    if (tid < BATCH) {
        float s = bout[0];
        #pragma unroll 8
        for (int j = 0; j < H2; j++)
            s += hid[j * BATCH + tid] * Wout[j];
        out[(size_t)t * BATCH + tid] = 1.0f / (1.0f + expf(-s));
    }
}

// =====================================================================
extern "C" void kernel_launch(void* const* d_in, const int* in_sizes, int n_in,
                              void* d_out, int out_size) {
    const float* word = (const float*)d_in[0];
    const float* Wih  = (const float*)d_in[1];
    const float* Whh  = (const float*)d_in[2];
    const float* bih  = (const float*)d_in[3];
    const float* bhh  = (const float*)d_in[4];
    const float* Wfc  = (const float*)d_in[5];
    const float* bfc  = (const float*)d_in[6];
    const float* Wout = (const float*)d_in[7];
    const float* bout = (const float*)d_in[8];
    float* out = (float*)d_out;

    cudaFuncSetAttribute(k_head, cudaFuncAttributeMaxDynamicSharedMemorySize, HEAD_SMEM_B);

    // order: k_xw(#3), noop(#4), noop(#5), k_rec(#6 <- ncu -s 5 capture), k_head(#7)
    k_xw<<<dim3(25, T_STEPS), 256>>>(word, Wih, bih, bhh);
    k_noop<<<1, 32>>>();
    k_noop<<<1, 32>>>();
    k_rec<<<GRID_R, 256>>>(Whh);
    k_head<<<T_STEPS, 256, HEAD_SMEM_B>>>(Wfc, bfc, Wout, bout, out);
}

// round 15
// speedup vs baseline: 1.8694x; 1.2085x over previous
#include <cuda_runtime.h>
#include <math.h>

#define T_STEPS 2048
#define BATCH   64
#define IN_DIM  27
#define H1      400
#define H2      200
#define GRID_R  148          // 104 x 3 units + 44 x 2 units = 400
#define K4      (H1 / 4)
#define NSHARD  8

// ---------------- device scratch (static; zero-init) ----------------
static __device__ float g_xw[(size_t)T_STEPS * 4 * H1 * BATCH];   // [t][row1600][b]
static __device__ float g_hr[(size_t)(T_STEPS + 1) * H1 * BATCH]; // [t][k>>2][b][k&3]
static __device__ unsigned int g_bars[NSHARD * 32];                // shards 128B apart

__device__ __forceinline__ void ffma2(unsigned long long &acc,
                                      unsigned long long a, unsigned long long b) {
    asm("fma.rn.f32x2 %0, %1, %2, %0;" : "+l"(acc) : "l"(a), "l"(b));
}
__device__ __forceinline__ float lo32(unsigned long long v) { return __uint_as_float((unsigned)v); }
__device__ __forceinline__ float hi32(unsigned long long v) { return __uint_as_float((unsigned)(v >> 32)); }

__device__ __forceinline__ unsigned ld_acq(const unsigned* p) {
    unsigned v;
    asm volatile("ld.acquire.gpu.u32 %0, [%1];" : "=r"(v) : "l"(p));
    return v;
}

// profiling spacer (with 2 harness pre-launches, order below puts k_rec at #6 for -s 5)
__global__ void k_noop() {}

// =====================================================================
// Kernel 1: xw[t][r][b] = word[t,b,:] . W_ih[r,:] + b_ih[r] + b_hh[r]
// grid (25, 2048), block 256. Also resets the sharded barrier counters.
// =====================================================================
__global__ void __launch_bounds__(256) k_xw(const float* __restrict__ word,
                                            const float* __restrict__ Wih,
                                            const float* __restrict__ bih,
                                            const float* __restrict__ bhh) {
    __shared__ float xs[IN_DIM * 68];
    __shared__ float ws[64 * 28];
    __shared__ float bs[64];
    const int t = blockIdx.y;
    const int rbase = blockIdx.x * 64;
    const int tid = threadIdx.x;

    if (blockIdx.x == 0 && blockIdx.y == 0 && tid < NSHARD * 32) g_bars[tid] = 0u;

    for (int j = tid; j < BATCH * IN_DIM; j += 256) {
        int b = j / IN_DIM, i = j - b * IN_DIM;
        xs[i * 68 + b] = word[(size_t)t * (BATCH * IN_DIM) + j];
    }
    for (int j = tid; j < 64 * IN_DIM; j += 256) {
        int r = j / IN_DIM, i = j - r * IN_DIM;
        ws[r * 28 + i] = Wih[(size_t)(rbase + r) * IN_DIM + i];
    }
    if (tid < 64) bs[tid] = bih[rbase + tid] + bhh[rbase + tid];
    __syncthreads();

    const int rq = tid >> 4;
    const int bq = (tid & 15) * 4;
    float acc[4][4];
    #pragma unroll
    for (int r = 0; r < 4; r++) {
        float bv = bs[rq * 4 + r];
        #pragma unroll
        for (int b = 0; b < 4; b++) acc[r][b] = bv;
    }
    #pragma unroll 3
    for (int i = 0; i < IN_DIM; i++) {
        float4 xv = *(const float4*)&xs[i * 68 + bq];
        #pragma unroll
        for (int r = 0; r < 4; r++) {
            float w = ws[(rq * 4 + r) * 28 + i];
            acc[r][0] += w * xv.x; acc[r][1] += w * xv.y;
            acc[r][2] += w * xv.z; acc[r][3] += w * xv.w;
        }
    }
    size_t base = ((size_t)t * (4 * H1) + rbase) * BATCH;
    #pragma unroll
    for (int r = 0; r < 4; r++) {
        float4 v = make_float4(acc[r][0], acc[r][1], acc[r][2], acc[r][3]);
        *(float4*)&g_xw[base + (size_t)(rq * 4 + r) * BATCH + bq] = v;
    }
}

// =====================================================================
// Kernel 2: persistent recurrence. grid 148, block 256, 1 CTA/SM.
// EXACT champion structure (R3 submission, 16.4ms); ONLY change:
// single barrier counter -> 8 sharded counters (128B apart).
// Arrival: tid0 atomicAdd to shard (bid&7)  (~19 RMWs/shard vs 148/1).
// Wait: lanes 0..7 of warp 0 each poll one shard; then __syncthreads.
// =====================================================================
template<int NU>
__device__ __forceinline__ void rec_body(const float* __restrict__ Whh,
                                         int u0, int bid, float* ws, float* pr) {
    constexpr int R = 4 * NU;
    const int tid  = threadIdx.x;
    const int lane = tid & 31;
    const int wid  = tid >> 5;
    const int ks   = wid & 3;                // k-split 0..3 (25 k4 each)
    const int bg   = wid >> 2;               // batch group 0..1
    const int b    = bg * 32 + lane;

    for (int idx = tid; idx < R * H1; idx += 256) {
        int lr = idx / H1, k = idx - lr * H1;
        int g = lr / NU, q = lr - g * NU;
        ws[lr * H1 + k] = Whh[(size_t)(g * H1 + u0 + q) * H1 + k];
    }

    const int cb = tid & 63;
    const int q  = tid >> 6;
    const int uu = u0 + (q < NU ? q : NU - 1);
    const size_t hr_off = (size_t)(uu >> 2) * 256 + cb * 4 + (uu & 3);
    float c_val = 0.0f;

    // shard membership: shards 0..3 have 19 CTAs, 4..7 have 18 (148 total)
    const int  myshard  = bid & 7;
    const unsigned mycnt = (tid < 8) ? ((tid < 4) ? 19u : 18u) : 1u;

    __syncthreads();

    const int k4lo = ks * 25;

    for (int t = 0; t < T_STEPS; t++) {
        // ---- prefetch xw for combine (latency hidden under dots) ----
        float xw0 = 0.f, xw1 = 0.f, xw2 = 0.f, xw3 = 0.f;
        if (q < NU) {
            const float* xp = g_xw + (size_t)t * (4 * H1) * BATCH;
            xw0 = __ldcg(&xp[(size_t)(0 * H1 + uu) * BATCH + cb]);
            xw1 = __ldcg(&xp[(size_t)(1 * H1 + uu) * BATCH + cb]);
            xw2 = __ldcg(&xp[(size_t)(2 * H1 + uu) * BATCH + cb]);
            xw3 = __ldcg(&xp[(size_t)(3 * H1 + uu) * BATCH + cb]);
        }

        // ---- dots: acc[lr] over this warp's k-range (1-deep prefetch) ----
        unsigned long long acc[R];
        #pragma unroll
        for (int lr = 0; lr < R; lr++) acc[lr] = 0ull;

        const float* hbase = g_hr + (size_t)t * (H1 * BATCH);
        ulonglong2 h_cur = __ldcg((const ulonglong2*)(hbase + k4lo * 256 + b * 4));
        #pragma unroll 5
        for (int i = 0; i < 25; i++) {
            ulonglong2 h4 = h_cur;
            if (i < 24)
                h_cur = __ldcg((const ulonglong2*)(hbase + (k4lo + i + 1) * 256 + b * 4));
            const int k4 = k4lo + i;
            #pragma unroll
            for (int lr = 0; lr < R; lr++) {
                ulonglong2 w2 = *(const ulonglong2*)&ws[lr * H1 + k4 * 4];
                ffma2(acc[lr], h4.x, w2.x);
                ffma2(acc[lr], h4.y, w2.y);
            }
        }
        #pragma unroll
        for (int lr = 0; lr < R; lr++)
            pr[(ks * R + lr) * 64 + b] = lo32(acc[lr]) + hi32(acc[lr]);
        __syncthreads();

        // ---- combine: LSTM cell for (unit uu, batch cb) ----
        if (q < NU) {
            float g0 = xw0, g1 = xw1, g2 = xw2, g3 = xw3;
            #pragma unroll
            for (int s = 0; s < 4; s++) {
                g0 += pr[(s * R + 0 * NU + q) * 64 + cb];
                g1 += pr[(s * R + 1 * NU + q) * 64 + cb];
                g2 += pr[(s * R + 2 * NU + q) * 64 + cb];
                g3 += pr[(s * R + 3 * NU + q) * 64 + cb];
            }
            float iv = 1.0f / (1.0f + expf(-g0));
            float fv = 1.0f / (1.0f + expf(-g1));
            float gv = tanhf(g2);
            float ov = 1.0f / (1.0f + expf(-g3));
            float cn = fv * c_val + iv * gv;
            float hn = ov * tanhf(cn);
            c_val = fmaxf(cn, 0.0f);
            g_hr[(size_t)(t + 1) * (H1 * BATCH) + hr_off] = fmaxf(hn, 0.0f);
        }

        // ---- grid barrier: sharded arrivals + 8-lane poll ----
        __threadfence();
        __syncthreads();
        if (tid == 0)
            atomicAdd(&g_bars[myshard * 32], 1u);
        if (tid < 8) {
            const unsigned tgt = mycnt * (unsigned)(t + 1);
            const unsigned* sp = &g_bars[tid * 32];
            while (ld_acq(sp) < tgt) {}
        }
        __syncthreads();
    }
}

__global__ void __launch_bounds__(256, 1) k_rec(const float* __restrict__ Whh) {
    __shared__ float ws[12 * H1];
    __shared__ float pr[4 * 12 * 64];
    const int bid = blockIdx.x;
    if (bid < 104) rec_body<3>(Whh, bid * 3, bid, ws, pr);
    else           rec_body<2>(Whh, 312 + (bid - 104) * 2, bid, ws, pr);
}

// =====================================================================
// Kernel 3: MLP head per timestep. grid 2048, block 256.
// =====================================================================
#define HS_F 25600
#define HEAD_SMEM_B ((HS_F + H2 * BATCH) * 4)

__global__ void __launch_bounds__(256) k_head(const float* __restrict__ Wfc,
                                              const float* __restrict__ bfc,
                                              const float* __restrict__ Wout,
                                              const float* __restrict__ bout,
                                              float* __restrict__ out) {
    extern __shared__ float sm[];
    float* hs  = sm;
    float* hid = sm + HS_F;
    const int t = blockIdx.x;
    const int tid = threadIdx.x;

    const float4* hsrc = (const float4*)(g_hr + (size_t)(t + 1) * (H1 * BATCH));
    for (int i = tid; i < (H1 * BATCH) / 4; i += 256)
        ((float4*)hs)[i] = hsrc[i];
    __syncthreads();

    const int jrow = tid >> 4;
    const int bq   = (tid & 15) * 4;
    for (int j = jrow; j < H2; j += 16) {
        float bv = bfc[j];
        float4 acc = make_float4(bv, bv, bv, bv);
        const float4* wr = (const float4*)(Wfc + (size_t)j * H1);
        #pragma unroll 4
        for (int k4 = 0; k4 < K4; k4++) {
            float4 w4 = wr[k4];
            float4 h0 = *(const float4*)&hs[k4 * 256 + (bq + 0) * 4];
            float4 h1 = *(const float4*)&hs[k4 * 256 + (bq + 1) * 4];
            float4 h2 = *(const float4*)&hs[k4 * 256 + (bq + 2) * 4];
            float4 h3 = *(const float4*)&hs[k4 * 256 + (bq + 3) * 4];
            acc.x += w4.x * h0.x + w4.y * h0.y + w4.z * h0.z + w4.w * h0.w;
            acc.y += w4.x * h1.x + w4.y * h1.y + w4.z * h1.z + w4.w * h1.w;
            acc.z += w4.x * h2.x + w4.y * h2.y + w4.z * h2.z + w4.w * h2.w;
            acc.w += w4.x * h3.x + w4.y * h3.y + w4.z * h3.z + w4.w * h3.w;
        }
        acc.x = fmaxf(acc.x, 0.f); acc.y = fmaxf(acc.y, 0.f);
        acc.z = fmaxf(acc.z, 0.f); acc.w = fmaxf(acc.w, 0.f);
        *(float4*)&hid[j * BATCH + bq] = acc;
    }
    __syncthreads();

    if (tid < BATCH) {
        float s = bout[0];
        #pragma unroll 8
        for (int j = 0; j < H2; j++)
            s += hid[j * BATCH + tid] * Wout[j];
        out[(size_t)t * BATCH + tid] = 1.0f / (1.0f + expf(-s));
    }
}

// =====================================================================
extern "C" void kernel_launch(void* const* d_in, const int* in_sizes, int n_in,
                              void* d_out, int out_size) {
    const float* word = (const float*)d_in[0];
    const float* Wih  = (const float*)d_in[1];
    const float* Whh  = (const float*)d_in[2];
    const float* bih  = (const float*)d_in[3];
    const float* bhh  = (const float*)d_in[4];
    const float* Wfc  = (const float*)d_in[5];
    const float* bfc  = (const float*)d_in[6];
    const float* Wout = (const float*)d_in[7];
    const float* bout = (const float*)d_in[8];
    float* out = (float*)d_out;

    cudaFuncSetAttribute(k_head, cudaFuncAttributeMaxDynamicSharedMemorySize, HEAD_SMEM_B);

    // order: k_xw(#3), noop(#4), noop(#5), k_rec(#6 <- ncu -s 5 capture), k_head(#7)
    k_xw<<<dim3(25, T_STEPS), 256>>>(word, Wih, bih, bhh);
    k_noop<<<1, 32>>>();
    k_noop<<<1, 32>>>();
    k_rec<<<GRID_R, 256>>>(Whh);
    k_head<<<T_STEPS, 256, HEAD_SMEM_B>>>(Wfc, bfc, Wout, bout, out);
}

// round 16
// speedup vs baseline: 1.9313x; 1.0331x over previous
#include <cuda_runtime.h>
#include <math.h>

#define T_STEPS 2048
#define BATCH   64
#define IN_DIM  27
#define H1      400
#define H2      200
#define GRID_R  148          // 104 x 3 units + 44 x 2 units = 400
#define K4      (H1 / 4)
#define NSHARD  8

// ---------------- device scratch (static; zero-init) ----------------
static __device__ float g_xw[(size_t)T_STEPS * 4 * H1 * BATCH];   // [t][row1600][b]
static __device__ float g_hr[(size_t)(T_STEPS + 1) * H1 * BATCH]; // [t][k>>2][b][k&3]
static __device__ unsigned int g_bars[NSHARD * 32];                // shards 128B apart

__device__ __forceinline__ void ffma2(unsigned long long &acc,
                                      unsigned long long a, unsigned long long b) {
    asm("fma.rn.f32x2 %0, %1, %2, %0;" : "+l"(acc) : "l"(a), "l"(b));
}
__device__ __forceinline__ float lo32(unsigned long long v) { return __uint_as_float((unsigned)v); }
__device__ __forceinline__ float hi32(unsigned long long v) { return __uint_as_float((unsigned)(v >> 32)); }

__device__ __forceinline__ unsigned ld_acq(const unsigned* p) {
    unsigned v;
    asm volatile("ld.acquire.gpu.u32 %0, [%1];" : "=r"(v) : "l"(p));
    return v;
}

// profiling spacer (with 2 harness pre-launches, order below puts k_rec at #6 for -s 5)
__global__ void k_noop() {}

// =====================================================================
// Kernel 1: xw[t][r][b] = word[t,b,:] . W_ih[r,:] + b_ih[r] + b_hh[r]
// grid (25, 2048), block 256. Also resets the sharded barrier counters.
// =====================================================================
__global__ void __launch_bounds__(256) k_xw(const float* __restrict__ word,
                                            const float* __restrict__ Wih,
                                            const float* __restrict__ bih,
                                            const float* __restrict__ bhh) {
    __shared__ float xs[IN_DIM * 68];
    __shared__ float ws[64 * 28];
    __shared__ float bs[64];
    const int t = blockIdx.y;
    const int rbase = blockIdx.x * 64;
    const int tid = threadIdx.x;

    if (blockIdx.x == 0 && blockIdx.y == 0 && tid < NSHARD * 32) g_bars[tid] = 0u;

    for (int j = tid; j < BATCH * IN_DIM; j += 256) {
        int b = j / IN_DIM, i = j - b * IN_DIM;
        xs[i * 68 + b] = word[(size_t)t * (BATCH * IN_DIM) + j];
    }
    for (int j = tid; j < 64 * IN_DIM; j += 256) {
        int r = j / IN_DIM, i = j - r * IN_DIM;
        ws[r * 28 + i] = Wih[(size_t)(rbase + r) * IN_DIM + i];
    }
    if (tid < 64) bs[tid] = bih[rbase + tid] + bhh[rbase + tid];
    __syncthreads();

    const int rq = tid >> 4;
    const int bq = (tid & 15) * 4;
    float acc[4][4];
    #pragma unroll
    for (int r = 0; r < 4; r++) {
        float bv = bs[rq * 4 + r];
        #pragma unroll
        for (int b = 0; b < 4; b++) acc[r][b] = bv;
    }
    #pragma unroll 3
    for (int i = 0; i < IN_DIM; i++) {
        float4 xv = *(const float4*)&xs[i * 68 + bq];
        #pragma unroll
        for (int r = 0; r < 4; r++) {
            float w = ws[(rq * 4 + r) * 28 + i];
            acc[r][0] += w * xv.x; acc[r][1] += w * xv.y;
            acc[r][2] += w * xv.z; acc[r][3] += w * xv.w;
        }
    }
    size_t base = ((size_t)t * (4 * H1) + rbase) * BATCH;
    #pragma unroll
    for (int r = 0; r < 4; r++) {
        float4 v = make_float4(acc[r][0], acc[r][1], acc[r][2], acc[r][3]);
        *(float4*)&g_xw[base + (size_t)(rq * 4 + r) * BATCH + bq] = v;
    }
}

// =====================================================================
// Kernel 2: persistent recurrence. grid 148, block 512 (16 warps), 1 CTA/SM.
// Same structure as the 16.35ms champion; ONLY change: 8 k-splits x 2
// batch-groups (4 warps/SMSP for latency hiding) instead of 4 x 2.
// static smem: ws[R<=12][400] | pr[8][R][64]
// =====================================================================
template<int NU>
__device__ __forceinline__ void rec_body(const float* __restrict__ Whh,
                                         int u0, int bid, float* ws, float* pr) {
    constexpr int R = 4 * NU;
    const int tid  = threadIdx.x;
    const int lane = tid & 31;
    const int wid  = tid >> 5;
    const int ks   = wid & 7;                // k-split 0..7 (13/12 quads)
    const int bg   = wid >> 3;               // batch group 0..1
    const int b    = bg * 32 + lane;

    for (int idx = tid; idx < R * H1; idx += 512) {
        int lr = idx / H1, k = idx - lr * H1;
        int g = lr / NU, q = lr - g * NU;
        ws[lr * H1 + k] = Whh[(size_t)(g * H1 + u0 + q) * H1 + k];
    }

    const int cb = tid & 63;
    const int q  = tid >> 6;                 // 0..7; active if < NU
    const int uu = u0 + (q < NU ? q : NU - 1);
    const size_t hr_off = (size_t)(uu >> 2) * 256 + cb * 4 + (uu & 3);
    float c_val = 0.0f;

    // shard membership: shards 0..3 have 19 CTAs, 4..7 have 18 (148 total)
    const int  myshard  = bid & 7;
    const unsigned mycnt = (tid < 8) ? ((tid < 4) ? 19u : 18u) : 1u;

    __syncthreads();

    const int nk4  = (ks < 4) ? 13 : 12;
    const int k4lo = (ks < 4) ? ks * 13 : 52 + (ks - 4) * 12;

    for (int t = 0; t < T_STEPS; t++) {
        // ---- prefetch xw for combine (latency hidden under dots) ----
        float xw0 = 0.f, xw1 = 0.f, xw2 = 0.f, xw3 = 0.f;
        if (q < NU) {
            const float* xp = g_xw + (size_t)t * (4 * H1) * BATCH;
            xw0 = __ldcg(&xp[(size_t)(0 * H1 + uu) * BATCH + cb]);
            xw1 = __ldcg(&xp[(size_t)(1 * H1 + uu) * BATCH + cb]);
            xw2 = __ldcg(&xp[(size_t)(2 * H1 + uu) * BATCH + cb]);
            xw3 = __ldcg(&xp[(size_t)(3 * H1 + uu) * BATCH + cb]);
        }

        // ---- dots: acc[lr] over this warp's k-range (1-deep prefetch) ----
        unsigned long long acc[R];
        #pragma unroll
        for (int lr = 0; lr < R; lr++) acc[lr] = 0ull;

        const float* hbase = g_hr + (size_t)t * (H1 * BATCH);
        ulonglong2 h_cur = __ldcg((const ulonglong2*)(hbase + k4lo * 256 + b * 4));
        #pragma unroll 4
        for (int i = 0; i < nk4; i++) {
            ulonglong2 h4 = h_cur;
            if (i + 1 < nk4)
                h_cur = __ldcg((const ulonglong2*)(hbase + (k4lo + i + 1) * 256 + b * 4));
            const int k4 = k4lo + i;
            #pragma unroll
            for (int lr = 0; lr < R; lr++) {
                ulonglong2 w2 = *(const ulonglong2*)&ws[lr * H1 + k4 * 4];
                ffma2(acc[lr], h4.x, w2.x);
                ffma2(acc[lr], h4.y, w2.y);
            }
        }
        #pragma unroll
        for (int lr = 0; lr < R; lr++)
            pr[(ks * R + lr) * 64 + b] = lo32(acc[lr]) + hi32(acc[lr]);
        __syncthreads();

        // ---- combine: LSTM cell for (unit uu, batch cb) ----
        if (q < NU) {
            float g0 = xw0, g1 = xw1, g2 = xw2, g3 = xw3;
            #pragma unroll
            for (int s = 0; s < 8; s++) {
                g0 += pr[(s * R + 0 * NU + q) * 64 + cb];
                g1 += pr[(s * R + 1 * NU + q) * 64 + cb];
                g2 += pr[(s * R + 2 * NU + q) * 64 + cb];
                g3 += pr[(s * R + 3 * NU + q) * 64 + cb];
            }
            float iv = 1.0f / (1.0f + expf(-g0));
            float fv = 1.0f / (1.0f + expf(-g1));
            float gv = tanhf(g2);
            float ov = 1.0f / (1.0f + expf(-g3));
            float cn = fv * c_val + iv * gv;
            float hn = ov * tanhf(cn);
            c_val = fmaxf(cn, 0.0f);
            g_hr[(size_t)(t + 1) * (H1 * BATCH) + hr_off] = fmaxf(hn, 0.0f);
        }

        // ---- grid barrier: sharded arrivals + 8-lane poll ----
        __threadfence();
        __syncthreads();
        if (tid == 0)
            atomicAdd(&g_bars[myshard * 32], 1u);
        if (tid < 8) {
            const unsigned tgt = mycnt * (unsigned)(t + 1);
            const unsigned* sp = &g_bars[tid * 32];
            while (ld_acq(sp) < tgt) {}
        }
        __syncthreads();
    }
}

__global__ void __launch_bounds__(512, 1) k_rec(const float* __restrict__ Whh) {
    __shared__ float ws[12 * H1];        // 19.2 KB
    __shared__ float pr[8 * 12 * 64];    // 24.6 KB
    const int bid = blockIdx.x;
    if (bid < 104) rec_body<3>(Whh, bid * 3, bid, ws, pr);
    else           rec_body<2>(Whh, 312 + (bid - 104) * 2, bid, ws, pr);
}

// =====================================================================
// Kernel 3: MLP head per timestep. grid 2048, block 256.
// =====================================================================
#define HS_F 25600
#define HEAD_SMEM_B ((HS_F + H2 * BATCH) * 4)

__global__ void __launch_bounds__(256) k_head(const float* __restrict__ Wfc,
                                              const float* __restrict__ bfc,
                                              const float* __restrict__ Wout,
                                              const float* __restrict__ bout,
                                              float* __restrict__ out) {
    extern __shared__ float sm[];
    float* hs  = sm;
    float* hid = sm + HS_F;
    const int t = blockIdx.x;
    const int tid = threadIdx.x;

    const float4* hsrc = (const float4*)(g_hr + (size_t)(t + 1) * (H1 * BATCH));
    for (int i = tid; i < (H1 * BATCH) / 4; i += 256)
        ((float4*)hs)[i] = hsrc[i];
    __syncthreads();

    const int jrow = tid >> 4;
    const int bq   = (tid & 15) * 4;
    for (int j = jrow; j < H2; j += 16) {
        float bv = bfc[j];
        float4 acc = make_float4(bv, bv, bv, bv);
        const float4* wr = (const float4*)(Wfc + (size_t)j * H1);
        #pragma unroll 4
        for (int k4 = 0; k4 < K4; k4++) {
            float4 w4 = wr[k4];
            float4 h0 = *(const float4*)&hs[k4 * 256 + (bq + 0) * 4];
            float4 h1 = *(const float4*)&hs[k4 * 256 + (bq + 1) * 4];
            float4 h2 = *(const float4*)&hs[k4 * 256 + (bq + 2) * 4];
            float4 h3 = *(const float4*)&hs[k4 * 256 + (bq + 3) * 4];
            acc.x += w4.x * h0.x + w4.y * h0.y + w4.z * h0.z + w4.w * h0.w;
            acc.y += w4.x * h1.x + w4.y * h1.y + w4.z * h1.z + w4.w * h1.w;
            acc.z += w4.x * h2.x + w4.y * h2.y + w4.z * h2.z + w4.w * h2.w;
            acc.w += w4.x * h3.x + w4.y * h3.y + w4.z * h3.z + w4.w * h3.w;
        }
        acc.x = fmaxf(acc.x, 0.f); acc.y = fmaxf(acc.y, 0.f);
        acc.z = fmaxf(acc.z, 0.f); acc.w = fmaxf(acc.w, 0.f);
        *(float4*)&hid[j * BATCH + bq] = acc;
    }
    __syncthreads();

    if (tid < BATCH) {
        float s = bout[0];
        #pragma unroll 8
        for (int j = 0; j < H2; j++)
            s += hid[j * BATCH + tid] * Wout[j];
        out[(size_t)t * BATCH + tid] = 1.0f / (1.0f + expf(-s));
    }
}

// =====================================================================
extern "C" void kernel_launch(void* const* d_in, const int* in_sizes, int n_in,
                              void* d_out, int out_size) {
    const float* word = (const float*)d_in[0];
    const float* Wih  = (const float*)d_in[1];
    const float* Whh  = (const float*)d_in[2];
    const float* bih  = (const float*)d_in[3];
    const float* bhh  = (const float*)d_in[4];
    const float* Wfc  = (const float*)d_in[5];
    const float* bfc  = (const float*)d_in[6];
    const float* Wout = (const float*)d_in[7];
    const float* bout = (const float*)d_in[8];
    float* out = (float*)d_out;

    cudaFuncSetAttribute(k_head, cudaFuncAttributeMaxDynamicSharedMemorySize, HEAD_SMEM_B);

    // order: k_xw(#3), noop(#4), noop(#5), k_rec(#6 <- ncu -s 5 capture), k_head(#7)
    k_xw<<<dim3(25, T_STEPS), 256>>>(word, Wih, bih, bhh);
    k_noop<<<1, 32>>>();
    k_noop<<<1, 32>>>();
    k_rec<<<GRID_R, 512>>>(Whh);
    k_head<<<T_STEPS, 256, HEAD_SMEM_B>>>(Wfc, bfc, Wout, bout, out);
}